// round 8
// baseline (speedup 1.0000x reference)
#include <cuda_runtime.h>
#include <cuda_fp16.h>
#include <math.h>

// Problem constants
#define BATCH    64
#define IN_CAPS  2048
#define IN_DIM   16
#define NUM_CAPS 32
#define OUT_DIM  16
#define JD       512            // NUM_CAPS * OUT_DIM
#define NCHUNK   64             // i-chunks (32 i each) for partials
#define IC       (IN_CAPS/NCHUNK)  // 32 i per chunk

// Scratch (device globals; allocation-free per harness rules)
__device__ __align__(16) __half g_uhat[(size_t)BATCH * IN_CAPS * JD];   // 128 MB, [b][i][j*16+d]
__device__ float g_spart[(size_t)BATCH * NCHUNK * JD];  // 8 MB, d-major [b][c][d*32+j]
__device__ float g_out0[(size_t)BATCH * JD];            // d-major [b][d*32+j]
__device__ float g_out1[(size_t)BATCH * JD];

// ---- packed f32x2 helpers (sm_103a) ---------------------------------------
static __device__ __forceinline__ unsigned long long pack2(float lo, float hi) {
    unsigned long long r;
    asm("mov.b64 %0, {%1, %2};" : "=l"(r) : "f"(lo), "f"(hi));
    return r;
}
#define FMA2(d, a, b, c) asm("fma.rn.f32x2 %0, %1, %2, %3;" : "=l"(d) : "l"(a), "l"(b), "l"(c))
#define MUL2(d, a, b)    asm("mul.rn.f32x2 %0, %1, %2;"     : "=l"(d) : "l"(a), "l"(b))
#define ADD2(d, a, b)    asm("add.rn.f32x2 %0, %1, %2;"     : "=l"(d) : "l"(a), "l"(b))
#define UNPK2(lo, hi, v) asm("mov.b64 {%0, %1}, %2;" : "=f"(lo), "=f"(hi) : "l"(v))

// ---------------------------------------------------------------------------
// K1 fused: compute u_hat (fp16 store) AND the iter-0 partial sums.
// Grid (64 i-chunks, 4 jd-quarters), 512 threads = 64 jd-pairs x 8 b-groups.
// All 64 batches live in the block -> W read exactly once globally.
// Per i: x row staged as (v,v) f32x2 pairs; W slice staged TRANSPOSED
// (wst[k][row]) so pair loads are conflict-free LDS.64. Double-buffered,
// one barrier per i. s0 partial accumulated in f32x2 regs over the 32 i's,
// written to g_spart (disjoint jd range per block -> no atomics).
// ---------------------------------------------------------------------------
__global__ __launch_bounds__(512) void uhat_s0_kernel(
    const float* __restrict__ x, const float* __restrict__ W)
{
    const int c   = blockIdx.x;       // i-chunk (32 i's)
    const int jq  = blockIdx.y;       // jd quarter (128 jd's)
    const int t   = threadIdx.x;
    const int bh  = t >> 6;           // 0..7 : batch group of 8
    const int pr  = t & 63;           // 0..63: jd-pair within quarter
    const int jd0 = jq * 128 + 2 * pr;

    __shared__ unsigned long long xs[2][BATCH][16];   // (v,v) x pairs, 16 KB
    __shared__ float wst[2][16][132];                 // transposed W slice, ~16.5 KB

    // loader roles
    const int bx0 = t >> 4, kx = t & 15;   // x: (b, k) ; also b+32
    const int wr  = t >> 2, wq = t & 3;    // W: local row 0..127, float4 col

    // prefetch i = 0
    int ig = c * IC;
    float  xv0 = x[((size_t)bx0        * IN_CAPS + ig) * IN_DIM + kx];
    float  xv1 = x[((size_t)(bx0 + 32) * IN_CAPS + ig) * IN_DIM + kx];
    float4 wv  = *(const float4*)(W + ((size_t)ig * JD + jq * 128 + wr) * IN_DIM + 4 * wq);

    unsigned long long acc_s[8];
    #pragma unroll
    for (int bb = 0; bb < 8; bb++) acc_s[bb] = 0ull;

    for (int i = 0; i < IC; i++) {
        const int buf = i & 1;
        ig = c * IC + i;

        xs[buf][bx0][kx]      = pack2(xv0, xv0);
        xs[buf][bx0 + 32][kx] = pack2(xv1, xv1);
        wst[buf][4 * wq + 0][wr] = wv.x;
        wst[buf][4 * wq + 1][wr] = wv.y;
        wst[buf][4 * wq + 2][wr] = wv.z;
        wst[buf][4 * wq + 3][wr] = wv.w;
        __syncthreads();

        if (i < IC - 1) {   // prefetch next i
            int ign = ig + 1;
            xv0 = x[((size_t)bx0        * IN_CAPS + ign) * IN_DIM + kx];
            xv1 = x[((size_t)(bx0 + 32) * IN_CAPS + ign) * IN_DIM + kx];
            wv  = *(const float4*)(W + ((size_t)ign * JD + jq * 128 + wr) * IN_DIM + 4 * wq);
        }

        // W pairs for this thread's two jd rows: conflict-light LDS.64
        unsigned long long wp[16];
        #pragma unroll
        for (int k = 0; k < 16; k++)
            wp[k] = *(const unsigned long long*)&wst[buf][k][2 * pr];

        #pragma unroll
        for (int bb = 0; bb < 8; bb++) {
            const int b = bh * 8 + bb;
            const ulonglong2* ap = (const ulonglong2*)xs[buf][b];  // broadcast reads
            ulonglong2 a0 = ap[0], a1 = ap[1], a2 = ap[2], a3 = ap[3];
            ulonglong2 a4 = ap[4], a5 = ap[5], a6 = ap[6], a7 = ap[7];
            unsigned long long u;
            MUL2(u, wp[0],  a0.x);
            FMA2(u, wp[1],  a0.y, u);
            FMA2(u, wp[2],  a1.x, u);
            FMA2(u, wp[3],  a1.y, u);
            FMA2(u, wp[4],  a2.x, u);
            FMA2(u, wp[5],  a2.y, u);
            FMA2(u, wp[6],  a3.x, u);
            FMA2(u, wp[7],  a3.y, u);
            FMA2(u, wp[8],  a4.x, u);
            FMA2(u, wp[9],  a4.y, u);
            FMA2(u, wp[10], a5.x, u);
            FMA2(u, wp[11], a5.y, u);
            FMA2(u, wp[12], a6.x, u);
            FMA2(u, wp[13], a6.y, u);
            FMA2(u, wp[14], a7.x, u);
            FMA2(u, wp[15], a7.y, u);
            ADD2(acc_s[bb], acc_s[bb], u);
            float lo, hi;
            UNPK2(lo, hi, u);
            *(__half2*)(g_uhat + ((size_t)b * IN_CAPS + ig) * JD + jd0)
                = __floats2half2_rn(lo, hi);
        }
    }

    // write iter-0 partials, d-major: pos = d*32 + j ; both jd's share j.
    const int j  = jd0 >> 4;
    const int d0 = jd0 & 15;
    #pragma unroll
    for (int bb = 0; bb < 8; bb++) {
        const int b = bh * 8 + bb;
        float lo, hi;
        UNPK2(lo, hi, acc_s[bb]);
        float* sp = g_spart + ((size_t)b * NCHUNK + c) * JD;
        sp[d0 * 32 + j]       = lo * (1.0f / NUM_CAPS);
        sp[(d0 + 1) * 32 + j] = hi * (1.0f / NUM_CAPS);
    }
}

// ---------------------------------------------------------------------------
// Fused routing iteration (iters 1 and 2 only). Lane = j; lane loads
// u_hat[b,i,lane,0:15] (32B). Agreement dot in half2; softmax over j without
// max subtraction (exact: shift-invariant, |a| small). Two i's in flight.
//   iter1 logits = <u, out0>;  iter2 logits = <u, out0 + out1>.
// Grid (NCHUNK=64, BATCH), 8 warps, IC=32 i's per block.
// ---------------------------------------------------------------------------
__global__ __launch_bounds__(256, 4) void iter_kernel(int iter)
{
    const int b    = blockIdx.y;
    const int ic   = blockIdx.x;
    const int t    = threadIdx.x;
    const int w    = t >> 5;
    const int lane = t & 31;            // = j
    const int i0   = ic * IC;

    __half2 vout2[8];
    #pragma unroll
    for (int d2 = 0; d2 < 8; d2++) {
        float f0 = g_out0[(size_t)b * JD + (2 * d2)     * 32 + lane];
        float f1 = g_out0[(size_t)b * JD + (2 * d2 + 1) * 32 + lane];
        if (iter == 2) {
            f0 += g_out1[(size_t)b * JD + (2 * d2)     * 32 + lane];
            f1 += g_out1[(size_t)b * JD + (2 * d2 + 1) * 32 + lane];
        }
        vout2[d2] = __floats2half2_rn(f0, f1);
    }

    float acc[16];
    #pragma unroll
    for (int d = 0; d < 16; d++) acc[d] = 0.f;

    const __half* uhbase = g_uhat + ((size_t)b * IN_CAPS + i0) * JD + lane * 16;

    #pragma unroll
    for (int step = 0; step < 2; step++) {
        const int iiA = w + step * 16;
        const int iiB = iiA + 8;
        const uint4* pA = (const uint4*)(uhbase + (size_t)iiA * JD);
        const uint4* pB = (const uint4*)(uhbase + (size_t)iiB * JD);
        uint4 ra0 = pA[0], ra1 = pA[1];
        uint4 rb0 = pB[0], rb1 = pB[1];

        __half2 hA = __hmul2(((const __half2*)&ra0)[0], vout2[0]);
        __half2 hB = __hmul2(((const __half2*)&rb0)[0], vout2[0]);
        #pragma unroll
        for (int d2 = 1; d2 < 4; d2++) {
            hA = __hfma2(((const __half2*)&ra0)[d2], vout2[d2], hA);
            hB = __hfma2(((const __half2*)&rb0)[d2], vout2[d2], hB);
        }
        #pragma unroll
        for (int d2 = 0; d2 < 4; d2++) {
            hA = __hfma2(((const __half2*)&ra1)[d2], vout2[4 + d2], hA);
            hB = __hfma2(((const __half2*)&rb1)[d2], vout2[4 + d2], hB);
        }
        float eA = __expf(__low2float(hA) + __high2float(hA));
        float eB = __expf(__low2float(hB) + __high2float(hB));

        float sA = eA, sB = eB;   // single butterfly pair (no max pass)
        #pragma unroll
        for (int o = 16; o; o >>= 1) {
            sA += __shfl_xor_sync(0xffffffffu, sA, o);
            sB += __shfl_xor_sync(0xffffffffu, sB, o);
        }
        float cA = eA / sA;
        float cB = eB / sB;

        #pragma unroll
        for (int d2 = 0; d2 < 4; d2++) {
            float2 f = __half22float2(((const __half2*)&ra0)[d2]);
            acc[2 * d2]     = fmaf(cA, f.x, acc[2 * d2]);
            acc[2 * d2 + 1] = fmaf(cA, f.y, acc[2 * d2 + 1]);
            float2 g = __half22float2(((const __half2*)&ra1)[d2]);
            acc[8 + 2 * d2]     = fmaf(cA, g.x, acc[8 + 2 * d2]);
            acc[8 + 2 * d2 + 1] = fmaf(cA, g.y, acc[8 + 2 * d2 + 1]);
        }
        #pragma unroll
        for (int d2 = 0; d2 < 4; d2++) {
            float2 f = __half22float2(((const __half2*)&rb0)[d2]);
            acc[2 * d2]     = fmaf(cB, f.x, acc[2 * d2]);
            acc[2 * d2 + 1] = fmaf(cB, f.y, acc[2 * d2 + 1]);
            float2 g = __half22float2(((const __half2*)&rb1)[d2]);
            acc[8 + 2 * d2]     = fmaf(cB, g.x, acc[8 + 2 * d2]);
            acc[8 + 2 * d2 + 1] = fmaf(cB, g.y, acc[8 + 2 * d2 + 1]);
        }
    }

    // Cross-warp reduce (d-major in smem: conflict-free)
    __shared__ float red[8][JD];
    #pragma unroll
    for (int d = 0; d < 16; d++) red[w][d * 32 + lane] = acc[d];
    __syncthreads();

    float s1 = 0.f, s2 = 0.f;
    #pragma unroll
    for (int ww = 0; ww < 8; ww++) {
        s1 += red[ww][t];
        s2 += red[ww][t + 256];
    }
    float* sp = g_spart + ((size_t)b * NCHUNK + ic) * JD;
    sp[t]       = s1;
    sp[t + 256] = s2;
}

// ---------------------------------------------------------------------------
// Reduce partials over NCHUNK chunks + squash. d-major: t = d*32 + j.
// which: 0 -> g_out0, 1 -> g_out1, 2 -> dout (permuted to [b][j][d]).
// ---------------------------------------------------------------------------
__global__ __launch_bounds__(512) void squash_kernel(int which, float* __restrict__ dout)
{
    const int b = blockIdx.x;
    const int t = threadIdx.x;

    const float* sp = g_spart + (size_t)b * NCHUNK * JD + t;
    float s = 0.f;
    #pragma unroll
    for (int p = 0; p < NCHUNK; p++) s += sp[(size_t)p * JD];

    __shared__ float s2s[NUM_CAPS];
    if (t < NUM_CAPS) s2s[t] = 0.f;
    __syncthreads();
    atomicAdd(&s2s[t & 31], s * s);
    __syncthreads();

    float s2 = s2s[t & 31];
    float scale = s2 / ((1.0f + s2) * sqrtf(s2 + 1e-7f));
    float v = s * scale;

    if (which == 2)      dout[(size_t)b * JD + (t & 31) * 16 + (t >> 5)] = v;
    else if (which == 0) g_out0[(size_t)b * JD + t] = v;
    else                 g_out1[(size_t)b * JD + t] = v;
}

// ---------------------------------------------------------------------------
extern "C" void kernel_launch(void* const* d_in, const int* in_sizes, int n_in,
                              void* d_out, int out_size)
{
    const float* x = (const float*)d_in[0];
    const float* W = (const float*)d_in[1];
    if (in_sizes[0] == (int)((size_t)IN_CAPS * NUM_CAPS * IN_DIM * OUT_DIM)) {
        const float* tmp = x; x = W; W = tmp;
    }
    float* out = (float*)d_out;

    dim3 ug(NCHUNK, 4);
    dim3 ig(NCHUNK, BATCH);

    uhat_s0_kernel<<<ug, 512>>>(x, W);       // u_hat + iter-0 partials
    squash_kernel<<<BATCH, 512>>>(0, out);   // -> g_out0

    iter_kernel<<<ig, 256>>>(1);
    squash_kernel<<<BATCH, 512>>>(1, out);   // -> g_out1

    iter_kernel<<<ig, 256>>>(2);
    squash_kernel<<<BATCH, 512>>>(2, out);   // -> dout
}

// round 9
// speedup vs baseline: 1.4895x; 1.4895x over previous
#include <cuda_runtime.h>
#include <cuda_fp16.h>
#include <math.h>

// Problem constants
#define BATCH    64
#define IN_CAPS  2048
#define IN_DIM   16
#define NUM_CAPS 32
#define OUT_DIM  16
#define JD       512            // NUM_CAPS * OUT_DIM
#define NIC      32             // i-chunks per batch in iter kernel
#define IC       (IN_CAPS/NIC)  // 64 i's per block

// Scratch (device globals; allocation-free per harness rules)
__device__ __align__(16) __half g_uhat[(size_t)BATCH * IN_CAPS * JD];  // 128 MB, [b][i][j*16+d]
__device__ float g_spart[(size_t)BATCH * NIC * JD];  // 4 MB, d-major [b][ic][d*32+j]
__device__ float g_out0[(size_t)BATCH * JD];         // d-major [b][d*32+j]
__device__ float g_out1[(size_t)BATCH * JD];

// ---- packed f32x2 helpers (sm_103a) ---------------------------------------
static __device__ __forceinline__ unsigned long long pack2(float lo, float hi) {
    unsigned long long r;
    asm("mov.b64 %0, {%1, %2};" : "=l"(r) : "f"(lo), "f"(hi));
    return r;
}
#define FMA2(d, a, b, c) asm("fma.rn.f32x2 %0, %1, %2, %3;" : "=l"(d) : "l"(a), "l"(b), "l"(c))
#define MUL2(d, a, b)    asm("mul.rn.f32x2 %0, %1, %2;"     : "=l"(d) : "l"(a), "l"(b))

// ---------------------------------------------------------------------------
// K1 (proven R6 config, 58us): u_hat[b,i,jd] = sum_k W[i,jd,k] * x[b,i,k].
// One block per i, 512 threads (t = jd). x staged in smem pre-packed as
// (b, b+1) f32x2 pairs; W row held in regs as (w,w) pairs. fma.rn.f32x2
// computes 2 batches per 16 packed FMAs. Coalesced W float4 reads.
// ---------------------------------------------------------------------------
__global__ __launch_bounds__(512) void uhat_kernel(
    const float* __restrict__ x, const float* __restrict__ W)
{
    const int i = blockIdx.x;
    const int t = threadIdx.x;          // 0..511

    __shared__ unsigned long long xp[32][16];   // 32 b-pairs x 16 k

    {
        int p = t >> 4, k = t & 15;     // 512 threads cover all 32*16
        float lo = x[((size_t)(2 * p)     * IN_CAPS + i) * IN_DIM + k];
        float hi = x[((size_t)(2 * p + 1) * IN_CAPS + i) * IN_DIM + k];
        xp[p][k] = pack2(lo, hi);
    }

    const float4* Wr = (const float4*)(W + ((size_t)i * JD + t) * IN_DIM);
    float4 w0 = Wr[0], w1 = Wr[1], w2 = Wr[2], w3 = Wr[3];
    unsigned long long wp[16];
    wp[0]  = pack2(w0.x, w0.x); wp[1]  = pack2(w0.y, w0.y);
    wp[2]  = pack2(w0.z, w0.z); wp[3]  = pack2(w0.w, w0.w);
    wp[4]  = pack2(w1.x, w1.x); wp[5]  = pack2(w1.y, w1.y);
    wp[6]  = pack2(w1.z, w1.z); wp[7]  = pack2(w1.w, w1.w);
    wp[8]  = pack2(w2.x, w2.x); wp[9]  = pack2(w2.y, w2.y);
    wp[10] = pack2(w2.z, w2.z); wp[11] = pack2(w2.w, w2.w);
    wp[12] = pack2(w3.x, w3.x); wp[13] = pack2(w3.y, w3.y);
    wp[14] = pack2(w3.z, w3.z); wp[15] = pack2(w3.w, w3.w);

    __syncthreads();

    __half* out = g_uhat + (size_t)i * JD + t;
    #pragma unroll 4
    for (int p = 0; p < 32; p++) {
        const ulonglong2* ap = (const ulonglong2*)xp[p];
        ulonglong2 a0 = ap[0], a1 = ap[1], a2 = ap[2], a3 = ap[3];
        ulonglong2 a4 = ap[4], a5 = ap[5], a6 = ap[6], a7 = ap[7];
        unsigned long long acc;
        MUL2(acc, wp[0],  a0.x);
        FMA2(acc, wp[1],  a0.y, acc);
        FMA2(acc, wp[2],  a1.x, acc);
        FMA2(acc, wp[3],  a1.y, acc);
        FMA2(acc, wp[4],  a2.x, acc);
        FMA2(acc, wp[5],  a2.y, acc);
        FMA2(acc, wp[6],  a3.x, acc);
        FMA2(acc, wp[7],  a3.y, acc);
        FMA2(acc, wp[8],  a4.x, acc);
        FMA2(acc, wp[9],  a4.y, acc);
        FMA2(acc, wp[10], a5.x, acc);
        FMA2(acc, wp[11], a5.y, acc);
        FMA2(acc, wp[12], a6.x, acc);
        FMA2(acc, wp[13], a6.y, acc);
        FMA2(acc, wp[14], a7.x, acc);
        FMA2(acc, wp[15], a7.y, acc);
        float lo, hi;
        asm("mov.b64 {%0, %1}, %2;" : "=f"(lo), "=f"(hi) : "l"(acc));
        out[(size_t)(2 * p)     * IN_CAPS * JD] = __float2half_rn(lo);
        out[(size_t)(2 * p + 1) * IN_CAPS * JD] = __float2half_rn(hi);
    }
}

// ---------------------------------------------------------------------------
// Fused routing iteration (proven R7 config, 31.3us) + L2 ping-pong:
// rev flag reverses the block->(ic,b) mapping so this pass traverses u_hat
// in the opposite direction of the previous pass, hitting the ~126MB L2 on
// the predecessor's freshest lines instead of missing to DRAM.
// Lane = j; lane loads u_hat[b,i,lane,0:15] (32B). Agreement dot in half2;
// softmax over j without max subtraction (exact: shift-invariant, |a| small).
// Two i's in flight. iter1 logits = <u,out0>; iter2 logits = <u,out0+out1>.
// ---------------------------------------------------------------------------
__global__ __launch_bounds__(256, 4) void iter_kernel(int iter, int rev)
{
    const int b    = rev ? (BATCH - 1 - blockIdx.y) : blockIdx.y;
    const int ic   = rev ? (NIC - 1 - blockIdx.x)   : blockIdx.x;
    const int t    = threadIdx.x;
    const int w    = t >> 5;
    const int lane = t & 31;            // = j
    const int i0   = ic * IC;

    __half2 vout2[8];
    if (iter > 0) {
        #pragma unroll
        for (int d2 = 0; d2 < 8; d2++) {
            float f0 = g_out0[(size_t)b * JD + (2 * d2)     * 32 + lane];
            float f1 = g_out0[(size_t)b * JD + (2 * d2 + 1) * 32 + lane];
            if (iter == 2) {
                f0 += g_out1[(size_t)b * JD + (2 * d2)     * 32 + lane];
                f1 += g_out1[(size_t)b * JD + (2 * d2 + 1) * 32 + lane];
            }
            vout2[d2] = __floats2half2_rn(f0, f1);
        }
    }

    float acc[16];
    #pragma unroll
    for (int d = 0; d < 16; d++) acc[d] = 0.f;

    const __half* uhbase = g_uhat + ((size_t)b * IN_CAPS + i0) * JD + lane * 16;

    #pragma unroll
    for (int step = 0; step < 4; step++) {
        const int iiA = w + step * 16;
        const int iiB = iiA + 8;
        const uint4* pA = (const uint4*)(uhbase + (size_t)iiA * JD);
        const uint4* pB = (const uint4*)(uhbase + (size_t)iiB * JD);
        uint4 ra0 = pA[0], ra1 = pA[1];     // i = iiA : d 0..7, 8..15
        uint4 rb0 = pB[0], rb1 = pB[1];     // i = iiB

        if (iter == 0) {
            #pragma unroll
            for (int half_sel = 0; half_sel < 2; half_sel++) {
                const __half2* v2 = (const __half2*)(half_sel ? &rb0 : &ra0);
                const __half2* v3 = (const __half2*)(half_sel ? &rb1 : &ra1);
                #pragma unroll
                for (int d2 = 0; d2 < 4; d2++) {
                    float2 f = __half22float2(v2[d2]);
                    acc[2 * d2]     += f.x;
                    acc[2 * d2 + 1] += f.y;
                    float2 g = __half22float2(v3[d2]);
                    acc[8 + 2 * d2]     += g.x;
                    acc[8 + 2 * d2 + 1] += g.y;
                }
            }
        } else {
            // Agreement dots for both i's (independent chains, ILP)
            __half2 hA = __hmul2(((const __half2*)&ra0)[0], vout2[0]);
            __half2 hB = __hmul2(((const __half2*)&rb0)[0], vout2[0]);
            #pragma unroll
            for (int d2 = 1; d2 < 4; d2++) {
                hA = __hfma2(((const __half2*)&ra0)[d2], vout2[d2], hA);
                hB = __hfma2(((const __half2*)&rb0)[d2], vout2[d2], hB);
            }
            #pragma unroll
            for (int d2 = 0; d2 < 4; d2++) {
                hA = __hfma2(((const __half2*)&ra1)[d2], vout2[4 + d2], hA);
                hB = __hfma2(((const __half2*)&rb1)[d2], vout2[4 + d2], hB);
            }
            float eA = __expf(__low2float(hA) + __high2float(hA));
            float eB = __expf(__low2float(hB) + __high2float(hB));

            float sA = eA, sB = eB;   // interleaved butterflies (no max pass)
            #pragma unroll
            for (int o = 16; o; o >>= 1) {
                sA += __shfl_xor_sync(0xffffffffu, sA, o);
                sB += __shfl_xor_sync(0xffffffffu, sB, o);
            }
            float cA = eA / sA;
            float cB = eB / sB;

            #pragma unroll
            for (int d2 = 0; d2 < 4; d2++) {
                float2 f = __half22float2(((const __half2*)&ra0)[d2]);
                acc[2 * d2]     = fmaf(cA, f.x, acc[2 * d2]);
                acc[2 * d2 + 1] = fmaf(cA, f.y, acc[2 * d2 + 1]);
                float2 g = __half22float2(((const __half2*)&ra1)[d2]);
                acc[8 + 2 * d2]     = fmaf(cA, g.x, acc[8 + 2 * d2]);
                acc[8 + 2 * d2 + 1] = fmaf(cA, g.y, acc[8 + 2 * d2 + 1]);
            }
            #pragma unroll
            for (int d2 = 0; d2 < 4; d2++) {
                float2 f = __half22float2(((const __half2*)&rb0)[d2]);
                acc[2 * d2]     = fmaf(cB, f.x, acc[2 * d2]);
                acc[2 * d2 + 1] = fmaf(cB, f.y, acc[2 * d2 + 1]);
                float2 g = __half22float2(((const __half2*)&rb1)[d2]);
                acc[8 + 2 * d2]     = fmaf(cB, g.x, acc[8 + 2 * d2]);
                acc[8 + 2 * d2 + 1] = fmaf(cB, g.y, acc[8 + 2 * d2 + 1]);
            }
        }
    }

    if (iter == 0) {
        #pragma unroll
        for (int d = 0; d < 16; d++) acc[d] *= (1.0f / NUM_CAPS);
    }

    // Cross-warp reduce (d-major in smem: conflict-free)
    __shared__ float red[8][JD];
    #pragma unroll
    for (int d = 0; d < 16; d++) red[w][d * 32 + lane] = acc[d];
    __syncthreads();

    float s1 = 0.f, s2 = 0.f;
    #pragma unroll
    for (int ww = 0; ww < 8; ww++) {
        s1 += red[ww][t];
        s2 += red[ww][t + 256];
    }
    float* sp = g_spart + ((size_t)b * NIC + ic) * JD;
    sp[t]       = s1;
    sp[t + 256] = s2;
}

// ---------------------------------------------------------------------------
// Reduce partials over NIC chunks + squash. d-major positions: t = d*32 + j.
// which: 0 -> g_out0, 1 -> g_out1, 2 -> dout (permuted to [b][j][d]).
// ---------------------------------------------------------------------------
__global__ __launch_bounds__(512) void squash_kernel(int which, float* __restrict__ dout)
{
    const int b = blockIdx.x;
    const int t = threadIdx.x;

    const float* sp = g_spart + (size_t)b * NIC * JD + t;
    float s = 0.f;
    #pragma unroll
    for (int p = 0; p < NIC; p++) s += sp[(size_t)p * JD];

    __shared__ float s2s[NUM_CAPS];
    if (t < NUM_CAPS) s2s[t] = 0.f;
    __syncthreads();
    atomicAdd(&s2s[t & 31], s * s);
    __syncthreads();

    float s2 = s2s[t & 31];
    float scale = s2 / ((1.0f + s2) * sqrtf(s2 + 1e-7f));
    float v = s * scale;

    if (which == 2)      dout[(size_t)b * JD + (t & 31) * 16 + (t >> 5)] = v;
    else if (which == 0) g_out0[(size_t)b * JD + t] = v;
    else                 g_out1[(size_t)b * JD + t] = v;
}

// ---------------------------------------------------------------------------
extern "C" void kernel_launch(void* const* d_in, const int* in_sizes, int n_in,
                              void* d_out, int out_size)
{
    const float* x = (const float*)d_in[0];
    const float* W = (const float*)d_in[1];
    if (in_sizes[0] == (int)((size_t)IN_CAPS * NUM_CAPS * IN_DIM * OUT_DIM)) {
        const float* tmp = x; x = W; W = tmp;
    }
    float* out = (float*)d_out;

    dim3 ig(NIC, BATCH);

    // uhat writes ascending-i; alternate traversal direction each pass so the
    // start of every pass hits the L2-resident tail of the previous one.
    uhat_kernel<<<IN_CAPS, 512>>>(x, W);

    iter_kernel<<<ig, 256>>>(0, 1);          // reverse
    squash_kernel<<<BATCH, 512>>>(0, out);   // -> g_out0

    iter_kernel<<<ig, 256>>>(1, 0);          // forward
    squash_kernel<<<BATCH, 512>>>(1, out);   // -> g_out1

    iter_kernel<<<ig, 256>>>(2, 1);          // reverse
    squash_kernel<<<BATCH, 512>>>(2, out);   // -> dout
}